// round 14
// baseline (speedup 1.0000x reference)
#include <cuda_runtime.h>
#include <cuda_bf16.h>
#include <cstdint>

#define N_NODES 50000
#define N_EDGES 800000
#define D 64

// ---- device-global scratch (no allocations allowed) ----
__device__ __align__(16) float g_denom[N_NODES];
__device__ __align__(16) float g_hunnorm[N_NODES * D];   // un-normalized msg sums

// ---------------------------------------------------------------------------
// Fused edge kernel, 4 edges per half-warp (ILP=4). At the LTS traffic floor.
// ---------------------------------------------------------------------------
__global__ void __launch_bounds__(256) kgcn_edge_kernel(
        const float* __restrict__ h_src,
        const float* __restrict__ e,
        const int* __restrict__ src,
        const int* __restrict__ dst) {
    int tid = blockIdx.x * blockDim.x + threadIdx.x;
    int grp = tid >> 4;          // half-warp group id (200000 groups exactly)
    int sub = tid & 15;
    int eb  = grp * 4;

    int4 s4 = *reinterpret_cast<const int4*>(&src[eb]);
    int4 d4 = *reinterpret_cast<const int4*>(&dst[eb]);

    const float4* h4 = reinterpret_cast<const float4*>(h_src);
    const float4* e4 = reinterpret_cast<const float4*>(e);

    float4 ev0 = e4[(size_t)(eb + 0) * 16 + sub];
    float4 ev1 = e4[(size_t)(eb + 1) * 16 + sub];
    float4 ev2 = e4[(size_t)(eb + 2) * 16 + sub];
    float4 ev3 = e4[(size_t)(eb + 3) * 16 + sub];
    float4 hv0 = h4[(size_t)s4.x * 16 + sub];
    float4 hv1 = h4[(size_t)s4.y * 16 + sub];
    float4 hv2 = h4[(size_t)s4.z * 16 + sub];
    float4 hv3 = h4[(size_t)s4.w * 16 + sub];

    float t0 = hv0.x * ev0.x + hv0.y * ev0.y + hv0.z * ev0.z + hv0.w * ev0.w;
    float t1 = hv1.x * ev1.x + hv1.y * ev1.y + hv1.z * ev1.z + hv1.w * ev1.w;
    float t2 = hv2.x * ev2.x + hv2.y * ev2.y + hv2.z * ev2.z + hv2.w * ev2.w;
    float t3 = hv3.x * ev3.x + hv3.y * ev3.y + hv3.z * ev3.z + hv3.w * ev3.w;

    #pragma unroll
    for (int o = 1; o < 16; o <<= 1) {
        t0 += __shfl_xor_sync(0xffffffffu, t0, o);
        t1 += __shfl_xor_sync(0xffffffffu, t1, o);
        t2 += __shfl_xor_sync(0xffffffffu, t2, o);
        t3 += __shfl_xor_sync(0xffffffffu, t3, o);
    }

    float ex0 = __expf(t0);
    float ex1 = __expf(t1);
    float ex2 = __expf(t2);
    float ex3 = __expf(t3);

    float* a0 = &g_hunnorm[(size_t)d4.x * D + sub * 4];
    float* a1 = &g_hunnorm[(size_t)d4.y * D + sub * 4];
    float* a2 = &g_hunnorm[(size_t)d4.z * D + sub * 4];
    float* a3 = &g_hunnorm[(size_t)d4.w * D + sub * 4];
    asm volatile("red.global.add.v4.f32 [%0], {%1, %2, %3, %4};"
                 :: "l"(a0), "f"(ex0 * hv0.x), "f"(ex0 * hv0.y),
                    "f"(ex0 * hv0.z), "f"(ex0 * hv0.w) : "memory");
    asm volatile("red.global.add.v4.f32 [%0], {%1, %2, %3, %4};"
                 :: "l"(a1), "f"(ex1 * hv1.x), "f"(ex1 * hv1.y),
                    "f"(ex1 * hv1.z), "f"(ex1 * hv1.w) : "memory");
    asm volatile("red.global.add.v4.f32 [%0], {%1, %2, %3, %4};"
                 :: "l"(a2), "f"(ex2 * hv2.x), "f"(ex2 * hv2.y),
                    "f"(ex2 * hv2.z), "f"(ex2 * hv2.w) : "memory");
    asm volatile("red.global.add.v4.f32 [%0], {%1, %2, %3, %4};"
                 :: "l"(a3), "f"(ex3 * hv3.x), "f"(ex3 * hv3.y),
                    "f"(ex3 * hv3.z), "f"(ex3 * hv3.w) : "memory");
    if (sub == 0) {
        atomicAdd(&g_denom[d4.x], ex0);
        atomicAdd(&g_denom[d4.y], ex1);
        atomicAdd(&g_denom[d4.z], ex2);
        atomicAdd(&g_denom[d4.w], ex3);
    }
}

// ---------------------------------------------------------------------------
// TF32 helpers
// ---------------------------------------------------------------------------
__device__ __forceinline__ float tf32_rna(float x) {
    uint32_t r;
    asm("cvt.rna.tf32.f32 %0, %1;" : "=r"(r) : "f"(x));
    return __uint_as_float(r);
}

__device__ __forceinline__ void mma_tf32(float* d, const uint32_t* a,
                                         uint32_t b0, uint32_t b1) {
    asm volatile(
        "mma.sync.aligned.m16n8k8.row.col.f32.tf32.tf32.f32 "
        "{%0,%1,%2,%3}, {%4,%5,%6,%7}, {%8,%9}, {%0,%1,%2,%3};"
        : "+f"(d[0]), "+f"(d[1]), "+f"(d[2]), "+f"(d[3])
        : "r"(a[0]), "r"(a[1]), "r"(a[2]), "r"(a[3]), "r"(b0), "r"(b1));
}

// ---------------------------------------------------------------------------
// Output GEMM v5 (tensor cores, 3xTF32): out = concat(h_dst, hunnorm/denom)@W^T + b
// Block: 256 threads = 8 warps; 128-node x 64-col tile; warp: 16 rows x 64 cols.
// K processed in 4 chunks of 32 (chunks 0-1 = h_dst, 2-3 = normalized hunnorm).
// A (h) staged fp32 with stride 36 (conflict-free fragment LDS), split into
// big/small tf32 in registers. B (W chunk) pre-split big/small in smem,
// stride 72 (conflict-free). D = AbBb + AsBb + AbBs  (error ~ fp32).
// smem: 18KB (h) + 2x9KB (Wb,Ws) = 36KB.
// ---------------------------------------------------------------------------
#define HA_STR 36
#define WB_STR 72
__global__ void __launch_bounds__(256) kgcn_out_kernel(
        const float* __restrict__ h_dst,
        const float* __restrict__ W,
        const float* __restrict__ b,
        float* __restrict__ out) {
    __shared__ float h_s[128 * HA_STR];   // [node][kk] fp32, padded
    __shared__ float Wb_s[32 * WB_STR];   // [kk][n] big tf32 (as float)
    __shared__ float Ws_s[32 * WB_STR];   // [kk][n] small tf32

    const int tid  = threadIdx.x;
    const int lane = tid & 31;
    const int warp = tid >> 5;            // 0..7
    const int gid  = lane >> 2;           // 0..7
    const int tig  = lane & 3;            // 0..3
    const int m0   = warp * 16;
    const int node0 = blockIdx.x * 128;

    float acc[8][4];
    #pragma unroll
    for (int nt = 0; nt < 8; nt++)
        acc[nt][0] = acc[nt][1] = acc[nt][2] = acc[nt][3] = 0.f;

    #pragma unroll
    for (int c = 0; c < 4; c++) {
        const float* srcp = (c < 2) ? h_dst : g_hunnorm;
        const int kof4 = (c & 1) * 8;

        __syncthreads();   // previous chunk's readers done before overwrite
        // stage h chunk: 128 nodes x 32 k (1024 float4 loads, 4/thread)
        #pragma unroll
        for (int r = 0; r < 4; r++) {
            int idx = tid + r * 256;      // 0..1023
            int n   = idx >> 3;           // local node
            int q   = idx & 7;            // float4 k-slot
            int gn  = node0 + n;
            float4 v = make_float4(0.f, 0.f, 0.f, 0.f);
            if (gn < N_NODES) {
                v = reinterpret_cast<const float4*>(srcp)[(size_t)gn * 16 + kof4 + q];
                if (c >= 2) {
                    float dn = g_denom[gn];
                    float inv = (dn != 0.f) ? (1.0f / dn) : 0.f;  // edge-less -> 0
                    v.x *= inv; v.y *= inv; v.z *= inv; v.w *= inv;
                }
            }
            int base = n * HA_STR + q * 4;
            h_s[base + 0] = v.x; h_s[base + 1] = v.y;
            h_s[base + 2] = v.z; h_s[base + 3] = v.w;
        }
        // stage W chunk pre-split: B[k][n] = W[n*128 + c*32 + k]
        for (int i = tid; i < 32 * 64; i += 256) {
            int k = i >> 6;
            int n = i & 63;
            float w  = W[n * 128 + c * 32 + k];
            float wb = tf32_rna(w);
            float ws = tf32_rna(w - wb);
            Wb_s[k * WB_STR + n] = wb;
            Ws_s[k * WB_STR + n] = ws;
        }
        __syncthreads();

        #pragma unroll
        for (int ks = 0; ks < 4; ks++) {
            int kk0 = ks * 8;
            // A fragment (fp32), then split big/small in registers
            int ra = (m0 + gid) * HA_STR + kk0 + tig;
            int rb = (m0 + gid + 8) * HA_STR + kk0 + tig;
            float af0 = h_s[ra];
            float af1 = h_s[rb];
            float af2 = h_s[ra + 4];
            float af3 = h_s[rb + 4];
            float b0f = tf32_rna(af0), b1f = tf32_rna(af1);
            float b2f = tf32_rna(af2), b3f = tf32_rna(af3);
            uint32_t ab[4] = {__float_as_uint(b0f), __float_as_uint(b1f),
                              __float_as_uint(b2f), __float_as_uint(b3f)};
            uint32_t as[4] = {__float_as_uint(tf32_rna(af0 - b0f)),
                              __float_as_uint(tf32_rna(af1 - b1f)),
                              __float_as_uint(tf32_rna(af2 - b2f)),
                              __float_as_uint(tf32_rna(af3 - b3f))};
            int bbase = (kk0 + tig) * WB_STR + gid;
            #pragma unroll
            for (int nt = 0; nt < 8; nt++) {
                int bi = bbase + nt * 8;
                uint32_t bb0 = __float_as_uint(Wb_s[bi]);
                uint32_t bb1 = __float_as_uint(Wb_s[bi + 4 * WB_STR]);
                uint32_t bs0 = __float_as_uint(Ws_s[bi]);
                uint32_t bs1 = __float_as_uint(Ws_s[bi + 4 * WB_STR]);
                mma_tf32(acc[nt], ab, bb0, bb1);   // AbBb
                mma_tf32(acc[nt], as, bb0, bb1);   // AsBb
                mma_tf32(acc[nt], ab, bs0, bs1);   // AbBs
            }
        }
    }

    // epilogue: D[gid][2tig], D[gid][2tig+1], D[gid+8][...] per n-tile
    int gn0 = node0 + m0 + gid;
    int gn1 = gn0 + 8;
    #pragma unroll
    for (int nt = 0; nt < 8; nt++) {
        int col = nt * 8 + 2 * tig;
        float bv0 = b[col], bv1 = b[col + 1];
        if (gn0 < N_NODES) {
            float2 o = make_float2(acc[nt][0] + bv0, acc[nt][1] + bv1);
            *reinterpret_cast<float2*>(&out[(size_t)gn0 * 64 + col]) = o;
        }
        if (gn1 < N_NODES) {
            float2 o = make_float2(acc[nt][2] + bv0, acc[nt][3] + bv1);
            *reinterpret_cast<float2*>(&out[(size_t)gn1 * 64 + col]) = o;
        }
    }
}

// ---------------------------------------------------------------------------
// Launch.  Inputs: 0 h_src, 1 h_dst, 2 e, 3 src, 4 dst, 5 W, 6 b
// ---------------------------------------------------------------------------
extern "C" void kernel_launch(void* const* d_in, const int* in_sizes, int n_in,
                              void* d_out, int out_size) {
    const float* h_src = (const float*)d_in[0];
    const float* h_dst = (const float*)d_in[1];
    const float* e     = (const float*)d_in[2];
    const int*   src   = (const int*)d_in[3];
    const int*   dst   = (const int*)d_in[4];
    const float* W     = (const float*)d_in[5];
    const float* b     = (const float*)d_in[6];
    float* out = (float*)d_out;

    void* p_hunnorm = nullptr;
    void* p_denom   = nullptr;
    cudaGetSymbolAddress(&p_hunnorm, g_hunnorm);
    cudaGetSymbolAddress(&p_denom,   g_denom);
    cudaMemsetAsync(p_hunnorm, 0, sizeof(float) * N_NODES * D);
    cudaMemsetAsync(p_denom,   0, sizeof(float) * N_NODES);

    // 200000 half-warp groups * 4 edges; 16 groups per 256-thread block
    kgcn_edge_kernel<<<12500, 256>>>(h_src, e, src, dst);
    // 391 blocks of 128 nodes
    kgcn_out_kernel<<<(N_NODES + 127) / 128, 256>>>(h_dst, W, b, out);
}